// round 14
// baseline (speedup 1.0000x reference)
#include <cuda_runtime.h>
#include <cuda_fp16.h>
#include <cstdint>

#define B_  4
#define T_  2048
#define D_  1024
#define H_  16
#define DKH 64

// ---------------- scratch (static device globals; no runtime alloc) --------
__device__ __half g_qx[(size_t)B_ * T_ * D_];   // fp16 inputs
__device__ __half g_kx[(size_t)B_ * T_ * D_];
__device__ __half g_vx[(size_t)B_ * T_ * D_];
__device__ __half g_wh[4][(size_t)D_ * D_];     // fp16 weights [K,N]
__device__ __half g_qh[(size_t)B_ * T_ * D_];   // fp16 projections
__device__ __half g_kh[(size_t)B_ * T_ * D_];
__device__ __half g_vh[(size_t)B_ * T_ * D_];
__device__ __half g_ao[(size_t)B_ * T_ * D_];   // fp16 attention output
__device__ float  g_x [(size_t)B_ * T_ * D_];   // fp32 pre-LN
__device__ unsigned long long g_maskp[(size_t)B_ * T_ * (T_ / 64)];  // 2MB

// ---------------- cp.async / ldmatrix / mma helpers -------------------------
__device__ __forceinline__ void cp_async16(void* smem, const void* gmem) {
    unsigned s = (unsigned)__cvta_generic_to_shared(smem);
    asm volatile("cp.async.cg.shared.global [%0], [%1], 16;\n" :: "r"(s), "l"(gmem));
}
__device__ __forceinline__ void cp_async8(void* smem, const void* gmem) {
    unsigned s = (unsigned)__cvta_generic_to_shared(smem);
    asm volatile("cp.async.ca.shared.global [%0], [%1], 8;\n" :: "r"(s), "l"(gmem));
}
__device__ __forceinline__ void cp_commit() {
    asm volatile("cp.async.commit_group;\n");
}
template<int N>
__device__ __forceinline__ void cp_wait() {
    asm volatile("cp.async.wait_group %0;\n" :: "n"(N));
}
__device__ __forceinline__ void ldsm4(uint32_t* r, uint32_t a) {
    asm volatile("ldmatrix.sync.aligned.m8n8.x4.shared.b16 {%0,%1,%2,%3}, [%4];"
                 : "=r"(r[0]), "=r"(r[1]), "=r"(r[2]), "=r"(r[3]) : "r"(a));
}
__device__ __forceinline__ void ldsm4t(uint32_t* r, uint32_t a) {
    asm volatile("ldmatrix.sync.aligned.m8n8.x4.trans.shared.b16 {%0,%1,%2,%3}, [%4];"
                 : "=r"(r[0]), "=r"(r[1]), "=r"(r[2]), "=r"(r[3]) : "r"(a));
}
__device__ __forceinline__ void mma16816(float* c, const uint32_t* a, const uint32_t* b) {
    asm volatile(
        "mma.sync.aligned.m16n8k16.row.col.f32.f16.f16.f32 "
        "{%0,%1,%2,%3}, {%4,%5,%6,%7}, {%8,%9}, {%0,%1,%2,%3};"
        : "+f"(c[0]), "+f"(c[1]), "+f"(c[2]), "+f"(c[3])
        : "r"(a[0]), "r"(a[1]), "r"(a[2]), "r"(a[3]), "r"(b[0]), "r"(b[1]));
}
// pack two fp32 to fp16x2 (RTN)
__device__ __forceinline__ uint32_t pack_h2(float a, float b) {
    __half2 h = __floats2half2_rn(a, b);
    return *reinterpret_cast<uint32_t*>(&h);
}
// ex2 on fp16x2
__device__ __forceinline__ uint32_t ex2_h2(uint32_t t) {
    uint32_t r;
    asm volatile("ex2.approx.f16x2 %0, %1;" : "=r"(r) : "r"(t));
    return r;
}

// ---------------- mask bit-pack: one warp per 64-bit word -------------------
__global__ void pack_mask_kernel(const int* __restrict__ mask,
                                 unsigned long long* __restrict__ mp) {
    const int gw   = (blockIdx.x * blockDim.x + threadIdx.x) >> 5;
    const int lane = threadIdx.x & 31;
    const int* src = mask + (size_t)gw * 64;
    int v0 = src[lane];
    int v1 = src[lane + 32];
    unsigned lo = __ballot_sync(0xffffffffu, v0 != 0);
    unsigned hi = __ballot_sync(0xffffffffu, v1 != 0);
    if (lane == 0) mp[gw] = ((unsigned long long)hi << 32) | lo;
}

// ---------------- fp32 -> fp16 convert (batched) ----------------------------
__global__ void f2h3_kernel(const float* __restrict__ s0, __half* __restrict__ d0,
                            const float* __restrict__ s1, __half* __restrict__ d1,
                            const float* __restrict__ s2, __half* __restrict__ d2,
                            int n4) {
    int i = blockIdx.x * blockDim.x + threadIdx.x;
    if (i >= n4) return;
    const float* in = (blockIdx.y == 0) ? s0 : (blockIdx.y == 1) ? s1 : s2;
    __half* out     = (blockIdx.y == 0) ? d0 : (blockIdx.y == 1) ? d1 : d2;
    float4 v = ((const float4*)in)[i];
    ((__half2*)out)[2 * i + 0] = __floats2half2_rn(v.x, v.y);
    ((__half2*)out)[2 * i + 1] = __floats2half2_rn(v.z, v.w);
}
__global__ void f2h4_kernel(const float* __restrict__ s0, const float* __restrict__ s1,
                            const float* __restrict__ s2, const float* __restrict__ s3,
                            __half* __restrict__ dst, int n4) {
    int i = blockIdx.x * blockDim.x + threadIdx.x;
    if (i >= n4) return;
    const float* in = (blockIdx.y == 0) ? s0 : (blockIdx.y == 1) ? s1
                    : (blockIdx.y == 2) ? s2 : s3;
    __half* out = dst + (size_t)blockIdx.y * D_ * D_;
    float4 v = ((const float4*)in)[i];
    ((__half2*)out)[2 * i + 0] = __floats2half2_rn(v.x, v.y);
    ((__half2*)out)[2 * i + 1] = __floats2half2_rn(v.z, v.w);
}

// ---------------- GEMM v7: raw mma.sync, 128x128 tile, 4 warps, 3 CTAs/SM ---
template<bool OUT_HALF>
__device__ __forceinline__
void gemm7_body(const __half* __restrict__ A,
                const __half* __restrict__ W,
                const float* __restrict__ bias,
                const float* __restrict__ res,
                void* __restrict__ Cout,
                char* smraw) {
    constexpr int K = D_, N = D_;
    constexpr int LDA = 72, LDB = 136;
    constexpr int ASZ = 128 * LDA;          // halves per stage
    constexpr int BSZ = 64 * LDB;
    constexpr int NCH = K / 64;             // 16 k-chunks

    __half* sA = (__half*)smraw;            // 2 stages
    __half* sB = sA + 2 * ASZ;              // 2 stages

    const int tid  = threadIdx.x;
    const int warp = tid >> 5;
    const int lane = tid & 31;
    const int wr   = warp & 1;              // 64-row half
    const int wc   = warp >> 1;             // 64-col half
    const int lr   = lane & 15;
    const int lh   = (lane >> 4) & 1;
    const int gr   = lane >> 2;
    const int t4   = lane & 3;
    const int m0   = blockIdx.y * 128;
    const int n0   = blockIdx.x * 128;

    float acc[4][8][4];
    #pragma unroll
    for (int i = 0; i < 4; i++)
        #pragma unroll
        for (int j = 0; j < 8; j++)
            #pragma unroll
            for (int e = 0; e < 4; e++) acc[i][j][e] = 0.0f;

    auto load_chunk = [&](int ch, int st) {
        __half* a = sA + st * ASZ;
        __half* b = sB + st * BSZ;
        const int k0 = ch * 64;
        #pragma unroll
        for (int i = 0; i < 8; i++) {       // A: 128x64 halves = 1024 chunks
            int idx = tid + i * 128;
            int r = idx >> 3, c8 = idx & 7;
            cp_async16(a + r * LDA + c8 * 8, A + (size_t)(m0 + r) * K + k0 + c8 * 8);
        }
        #pragma unroll
        for (int i = 0; i < 8; i++) {       // B: 64x128 halves = 1024 chunks
            int idx = tid + i * 128;
            int r = idx >> 4, c8 = idx & 15;
            cp_async16(b + r * LDB + c8 * 8, W + (size_t)(k0 + r) * N + n0 + c8 * 8);
        }
        cp_commit();
    };

    load_chunk(0, 0);

    for (int ch = 0; ch < NCH; ch++) {
        cp_wait<0>();
        __syncthreads();
        if (ch + 1 < NCH) load_chunk(ch + 1, (ch + 1) & 1);

        const uint32_t aU = (uint32_t)__cvta_generic_to_shared(sA + (ch & 1) * ASZ);
        const uint32_t bU = (uint32_t)__cvta_generic_to_shared(sB + (ch & 1) * BSZ);

        #pragma unroll
        for (int kk = 0; kk < 4; kk++) {
            uint32_t af[4][4];
            uint32_t bf[4][4];
            #pragma unroll
            for (int i = 0; i < 4; i++)
                ldsm4(af[i], aU + 2u * ((wr * 64 + i * 16 + lr) * LDA + kk * 16 + lh * 8));
            #pragma unroll
            for (int j4 = 0; j4 < 4; j4++)
                ldsm4t(bf[j4], bU + 2u * ((kk * 16 + lr) * LDB + wc * 64 + j4 * 16 + lh * 8));
            #pragma unroll
            for (int i = 0; i < 4; i++)
                #pragma unroll
                for (int j = 0; j < 8; j++)
                    mma16816(acc[i][j], af[i], &bf[j >> 1][(j & 1) * 2]);
        }
    }

    // ---- epilogue: registers -> gmem, bias (+res) fused ----
    #pragma unroll
    for (int i = 0; i < 4; i++) {
        const size_t r0 = (size_t)(m0 + wr * 64 + i * 16 + gr);
        const size_t r1 = r0 + 8;
        #pragma unroll
        for (int j = 0; j < 8; j++) {
            const int c = n0 + wc * 64 + j * 8 + 2 * t4;
            float2 bb = *(const float2*)(bias + c);
            float v0 = acc[i][j][0] + bb.x, v1 = acc[i][j][1] + bb.y;
            float v2 = acc[i][j][2] + bb.x, v3 = acc[i][j][3] + bb.y;
            if (OUT_HALF) {
                *(__half2*)((__half*)Cout + r0 * N + c) = __floats2half2_rn(v0, v1);
                *(__half2*)((__half*)Cout + r1 * N + c) = __floats2half2_rn(v2, v3);
            } else {
                float2 ra = *(const float2*)(res + r0 * N + c);
                float2 rb = *(const float2*)(res + r1 * N + c);
                *(float2*)((float*)Cout + r0 * N + c) = make_float2(v0 + ra.x, v1 + ra.y);
                *(float2*)((float*)Cout + r1 * N + c) = make_float2(v2 + rb.x, v3 + rb.y);
            }
        }
    }
}

// fused QKV: blockIdx.z selects (A, W, bias, C)
__global__ __launch_bounds__(128, 3)
void gemm7_qkv_kernel(const __half* __restrict__ Aq, const __half* __restrict__ Ak,
                      const __half* __restrict__ Av, const __half* __restrict__ Wbase,
                      const float* __restrict__ bq, const float* __restrict__ bk,
                      const float* __restrict__ bv,
                      __half* __restrict__ Cq, __half* __restrict__ Ck,
                      __half* __restrict__ Cv) {
    extern __shared__ char smraw[];
    const int z = blockIdx.z;
    const __half* A = (z == 0) ? Aq : (z == 1) ? Ak : Av;
    const __half* W = Wbase + (size_t)z * D_ * D_;
    const float* bias = (z == 0) ? bq : (z == 1) ? bk : bv;
    __half* C = (z == 0) ? Cq : (z == 1) ? Ck : Cv;
    gemm7_body<true>(A, W, bias, nullptr, C, smraw);
}

// out-proj: fp32 out + residual
__global__ __launch_bounds__(128, 3)
void gemm7_o_kernel(const __half* __restrict__ A, const __half* __restrict__ W,
                    const float* __restrict__ bias, const float* __restrict__ res,
                    float* __restrict__ C) {
    extern __shared__ char smraw[];
    gemm7_body<false>(A, W, bias, res, C, smraw);
}

// ---------------- flash attention v9: 2 q-subtiles per CTA ------------------
// CTA covers 128 q-rows as two 64-row subtiles sharing each staged K/V tile,
// halving KV L2 traffic vs QR=64. 4 warps, 3 CTAs/SM. Per warp: 16 rows of
// EACH subtile. Softmax/mma paths identical to verified attn8.
__global__ __launch_bounds__(128, 3)
void attn9_kernel(const __half* __restrict__ Qh,
                  const __half* __restrict__ Kh,
                  const __half* __restrict__ Vh,
                  const unsigned long long* __restrict__ maskp,
                  __half* __restrict__ Out) {
    constexpr int QR = 128, KT = 64, LD = 72;
    constexpr int NT = T_ / KT;   // 32
    constexpr float L2E = 1.44269504f;

    extern __shared__ char smraw[];
    unsigned long long* Mp = (unsigned long long*)smraw;        // 2*128*8 = 2048
    __half* Qs = (__half*)(smraw + 2048);                       // 128*72*2 = 18432
    __half* Ks = Qs + QR * LD;                                  // 2 stages 64*72
    __half* Vs = Ks + 2 * KT * LD;                              // 2 stages 64*72
    // total 57344 B -> 3 CTAs/SM

    const int tid  = threadIdx.x;
    const int warp = tid >> 5;
    const int lane = tid & 31;
    const int q0   = blockIdx.x * QR;
    const int h    = blockIdx.y;
    const int b    = blockIdx.z;

    const int lr  = lane & 15;
    const int l7  = lane & 7;
    const int lh  = (lane >> 4) & 1;
    const int l8  = (lane >> 3) & 1;
    const int gr  = lane >> 2;
    const int t4  = lane & 3;

    const __half* Qg = Qh + ((size_t)b * T_ + q0) * D_ + h * DKH;

    // Q -> smem (128x64 halves = 1024 16B chunks, 128 threads)
    #pragma unroll
    for (int i = 0; i < 8; i++) {
        int idx = tid + i * 128;
        int r = idx >> 3, c8 = idx & 7;
        cp_async16(Qs + r * LD + c8 * 8, Qg + (size_t)r * D_ + c8 * 8);
    }

    auto load_kv = [&](int kt, int p) {
        const int k0 = kt * KT;
        const __half* Kg = Kh + ((size_t)b * T_ + k0) * D_ + h * DKH;
        const __half* Vg = Vh + ((size_t)b * T_ + k0) * D_ + h * DKH;
        __half* kd = Ks + p * KT * LD;
        __half* vd = Vs + p * KT * LD;
        #pragma unroll
        for (int i = 0; i < 4; i++) {
            int idx = tid + i * 128;
            int r = idx >> 3, c8 = idx & 7;
            cp_async16(kd + r * LD + c8 * 8, Kg + (size_t)r * D_ + c8 * 8);
            cp_async16(vd + r * LD + c8 * 8, Vg + (size_t)r * D_ + c8 * 8);
        }
        // 128 mask rows for this tile
        cp_async8(&Mp[p * QR + tid],
                  &maskp[((size_t)b * T_ + q0 + tid) * (T_ / 64) + kt]);
        cp_commit();
    };

    load_kv(0, 0);      // commits Q chunks too

    const uint32_t QsB = (uint32_t)__cvta_generic_to_shared(Qs);
    const uint32_t KsB = (uint32_t)__cvta_generic_to_shared(Ks);
    const uint32_t VsB = (uint32_t)__cvta_generic_to_shared(Vs);
    const uint32_t ONES2 = 0x3C003C00u;
    const uint32_t ob[2] = {ONES2, ONES2};

    uint32_t qa[2][4][4];               // Q fragments for both subtiles
    float oc[2][8][4];                  // O accumulators
    float mr[2][2];                     // row max
    float lr_[2][2];                    // row sum
    #pragma unroll
    for (int t = 0; t < 2; t++) {
        #pragma unroll
        for (int j = 0; j < 8; j++)
            #pragma unroll
            for (int e = 0; e < 4; e++) oc[t][j][e] = 0.0f;
        mr[t][0] = -1e30f; mr[t][1] = -1e30f;
        lr_[t][0] = 0.0f;  lr_[t][1] = 0.0f;
    }

    for (int kt = 0; kt < NT; kt++) {
        const int p = kt & 1;
        cp_wait<0>();
        __syncthreads();
        if (kt == 0) {
            #pragma unroll
            for (int t = 0; t < 2; t++)
                #pragma unroll
                for (int kk = 0; kk < 4; kk++)
                    ldsm4(qa[t][kk],
                          QsB + 2u * ((t * 64 + warp * 16 + lr) * LD + kk * 16 + lh * 8));
        }
        if (kt + 1 < NT) load_kv(kt + 1, p ^ 1);

        const uint32_t KdB = KsB + (uint32_t)(p * KT * LD * 2);
        const uint32_t VdB = VsB + (uint32_t)(p * KT * LD * 2);

        #pragma unroll
        for (int t = 0; t < 2; t++) {
            // ---- S = Q_t @ K^T (16 rows x 64 keys) ----
            float sc[8][4];
            #pragma unroll
            for (int j = 0; j < 8; j++)
                #pragma unroll
                for (int e = 0; e < 4; e++) sc[j][e] = 0.0f;

            #pragma unroll
            for (int kk = 0; kk < 4; kk++) {
                #pragma unroll
                for (int jp = 0; jp < 4; jp++) {
                    uint32_t kb[4];
                    ldsm4(kb, KdB + 2u * ((16 * jp + l7 + lh * 8) * LD + kk * 16 + l8 * 8));
                    mma16816(sc[2 * jp],     qa[t][kk], kb);
                    mma16816(sc[2 * jp + 1], qa[t][kk], kb + 2);
                }
            }

            // ---- row max over UNMASKED S ----
            float mx0 = -1e30f, mx1 = -1e30f;
            #pragma unroll
            for (int j = 0; j < 8; j++) {
                mx0 = fmaxf(mx0, fmaxf(sc[j][0], sc[j][1]));
                mx1 = fmaxf(mx1, fmaxf(sc[j][2], sc[j][3]));
            }
            mx0 = fmaxf(mx0, __shfl_xor_sync(0xffffffffu, mx0, 1));
            mx0 = fmaxf(mx0, __shfl_xor_sync(0xffffffffu, mx0, 2));
            mx1 = fmaxf(mx1, __shfl_xor_sync(0xffffffffu, mx1, 1));
            mx1 = fmaxf(mx1, __shfl_xor_sync(0xffffffffu, mx1, 2));

            const float mn0 = fmaxf(mr[t][0], mx0);
            const float mn1 = fmaxf(mr[t][1], mx1);
            const float al0 = __expf(mr[t][0] - mn0);
            const float al1 = __expf(mr[t][1] - mn1);
            mr[t][0] = mn0; mr[t][1] = mn1;
            const float nm0 = mn0 * L2E;
            const float nm1 = mn1 * L2E;

            // ---- p = ex2((s-m)*log2e) fp16x2, masked -> 0 ----
            const unsigned long long mm0 = Mp[p * QR + t * 64 + warp * 16 + gr];
            const unsigned long long mm1 = Mp[p * QR + t * 64 + warp * 16 + gr + 8];
            uint32_t pa[4][4];
            #pragma unroll
            for (int j = 0; j < 8; j++) {
                const int c0 = 8 * j + 2 * t4;
                float t0 = ((mm0 >> c0) & 1ull)       ? fmaf(sc[j][0], L2E, -nm0) : -1e4f;
                float t1 = ((mm0 >> (c0 + 1)) & 1ull) ? fmaf(sc[j][1], L2E, -nm0) : -1e4f;
                float t2 = ((mm1 >> c0) & 1ull)       ? fmaf(sc[j][2], L2E, -nm1) : -1e4f;
                float t3 = ((mm1 >> (c0 + 1)) & 1ull) ? fmaf(sc[j][3], L2E, -nm1) : -1e4f;
                const int kk = j >> 1, lohalf = (j & 1) << 1;
                pa[kk][lohalf + 0] = ex2_h2(pack_h2(t0, t1));
                pa[kk][lohalf + 1] = ex2_h2(pack_h2(t2, t3));
            }

            // ---- row sum via tensor core: P @ ones ----
            float cs[4] = {0.0f, 0.0f, 0.0f, 0.0f};
            #pragma unroll
            for (int kk = 0; kk < 4; kk++)
                mma16816(cs, pa[kk], ob);
            lr_[t][0] = lr_[t][0] * al0 + cs[0];
            lr_[t][1] = lr_[t][1] * al1 + cs[2];

            #pragma unroll
            for (int j = 0; j < 8; j++) {
                oc[t][j][0] *= al0; oc[t][j][1] *= al0;
                oc[t][j][2] *= al1; oc[t][j][3] *= al1;
            }

            // ---- O += P @ V ----
            #pragma unroll
            for (int kk = 0; kk < 4; kk++) {
                #pragma unroll
                for (int jp = 0; jp < 4; jp++) {
                    uint32_t vb[4];
                    ldsm4t(vb, VdB + 2u * ((16 * kk + lr) * LD + 16 * jp + lh * 8));
                    mma16816(oc[t][2 * jp],     pa[kk], vb);
                    mma16816(oc[t][2 * jp + 1], pa[kk], vb + 2);
                }
            }
        }
    }

    // ---- epilogue: O / (l + 1e-15), direct to gmem (fp16) ----
    #pragma unroll
    for (int t = 0; t < 2; t++) {
        const float inv0 = 1.0f / (lr_[t][0] + 1e-15f);
        const float inv1 = 1.0f / (lr_[t][1] + 1e-15f);
        const size_t row0 = (size_t)b * T_ + q0 + t * 64 + warp * 16 + gr;
        __half* o0 = Out + row0 * D_ + h * DKH;
        __half* o1 = o0 + 8 * D_;
        #pragma unroll
        for (int j = 0; j < 8; j++) {
            const int c = 8 * j + 2 * t4;
            *(__half2*)(o0 + c) = __floats2half2_rn(oc[t][j][0] * inv0, oc[t][j][1] * inv0);
            *(__half2*)(o1 + c) = __floats2half2_rn(oc[t][j][2] * inv1, oc[t][j][3] * inv1);
        }
    }
}

// ---------------- LayerNorm over D=1024, one block per row -----------------
__global__ void ln_kernel(const float* __restrict__ X,
                          const float* __restrict__ gamma,
                          const float* __restrict__ beta,
                          float* __restrict__ Out) {
    const int row = blockIdx.x;
    const int tid = threadIdx.x;
    const float* x = X + (size_t)row * D_;

    __shared__ float red[8];
    __shared__ float s_mu, s_inv;

    float4 v = ((const float4*)x)[tid];
    float s = v.x + v.y + v.z + v.w;
    #pragma unroll
    for (int o = 16; o > 0; o >>= 1) s += __shfl_xor_sync(0xffffffffu, s, o);
    if ((tid & 31) == 0) red[tid >> 5] = s;
    __syncthreads();
    if (tid == 0) {
        float t = 0.0f;
        #pragma unroll
        for (int i = 0; i < 8; i++) t += red[i];
        s_mu = t * (1.0f / D_);
    }
    __syncthreads();
    const float mu = s_mu;

    float dx = v.x - mu, dy = v.y - mu, dz = v.z - mu, dw = v.w - mu;
    float s2 = dx * dx + dy * dy + dz * dz + dw * dw;
    #pragma unroll
    for (int o = 16; o > 0; o >>= 1) s2 += __shfl_xor_sync(0xffffffffu, s2, o);
    if ((tid & 31) == 0) red[tid >> 5] = s2;
    __syncthreads();
    if (tid == 0) {
        float t = 0.0f;
        #pragma unroll
        for (int i = 0; i < 8; i++) t += red[i];
        s_inv = rsqrtf(t * (1.0f / D_) + 1e-5f);
    }
    __syncthreads();
    const float inv = s_inv;

    const int c = tid * 4;
    float4 g = ((const float4*)(gamma + c))[0];
    float4 bb = ((const float4*)(beta + c))[0];
    float4 o;
    o.x = dx * inv * g.x + bb.x;
    o.y = dy * inv * g.y + bb.y;
    o.z = dz * inv * g.z + bb.z;
    o.w = dw * inv * g.w + bb.w;
    ((float4*)(Out + (size_t)row * D_))[tid] = o;
}

// ---------------- launch ----------------------------------------------------
extern "C" void kernel_launch(void* const* d_in, const int* in_sizes, int n_in,
                              void* d_out, int out_size) {
    const float* q     = (const float*)d_in[0];
    const float* k     = (const float*)d_in[1];
    const float* v     = (const float*)d_in[2];
    const int*   mask  = (const int*)  d_in[3];
    const float* Wq    = (const float*)d_in[4];
    const float* bq    = (const float*)d_in[5];
    const float* Wk    = (const float*)d_in[6];
    const float* bk    = (const float*)d_in[7];
    const float* Wv    = (const float*)d_in[8];
    const float* bv    = (const float*)d_in[9];
    const float* Wo    = (const float*)d_in[10];
    const float* bo    = (const float*)d_in[11];
    const float* gamma = (const float*)d_in[12];
    const float* beta  = (const float*)d_in[13];
    float* out = (float*)d_out;

    __half *qx, *kx, *vx, *wh, *qh, *kh, *vh, *ao;
    float *xb;
    unsigned long long* mp;
    cudaGetSymbolAddress((void**)&qx, g_qx);
    cudaGetSymbolAddress((void**)&kx, g_kx);
    cudaGetSymbolAddress((void**)&vx, g_vx);
    cudaGetSymbolAddress((void**)&wh, g_wh);
    cudaGetSymbolAddress((void**)&qh, g_qh);
    cudaGetSymbolAddress((void**)&kh, g_kh);
    cudaGetSymbolAddress((void**)&vh, g_vh);
    cudaGetSymbolAddress((void**)&ao, g_ao);
    cudaGetSymbolAddress((void**)&xb, g_x);
    cudaGetSymbolAddress((void**)&mp, g_maskp);

    __half* wo_h = wh + 3 * (size_t)D_ * D_;

    const int M = B_ * T_;   // 8192

    // pack mask to bits
    {
        const int words = B_ * T_ * (T_ / 64);
        pack_mask_kernel<<<words * 32 / 256, 256>>>(mask, mp);
    }

    // fp32 -> fp16 conversions (RTN), batched
    {
        const int n4a = (B_ * T_ * D_) / 4;
        dim3 ga(n4a / 256, 3);
        f2h3_kernel<<<ga, 256>>>(q, qx, k, kx, v, vx, n4a);
        const int n4w = (D_ * D_) / 4;
        dim3 gw(n4w / 256, 4);
        f2h4_kernel<<<gw, 256>>>(Wq, Wk, Wv, Wo, wh, n4w);
    }

    // mma.sync GEMMs (v7: 2-stage, direct register epilogue, 3 CTAs/SM)
    const int gemm_smem = 2 * (128 * 72 + 64 * 136) * 2;   // 71680 B
    cudaFuncSetAttribute(gemm7_qkv_kernel,
                         cudaFuncAttributeMaxDynamicSharedMemorySize, gemm_smem);
    cudaFuncSetAttribute(gemm7_o_kernel,
                         cudaFuncAttributeMaxDynamicSharedMemorySize, gemm_smem);

    dim3 gq(D_ / 128, M / 128, 3);   // (8, 64, 3)
    gemm7_qkv_kernel<<<gq, 128, gemm_smem>>>(qx, kx, vx, wh, bq, bk, bv,
                                             qh, kh, vh);

    // flash attention v9 (2 q-subtiles/CTA, 3 CTAs/SM)
    const int attn_smem = 2048 + 128 * 72 * 2 + 2 * (2 * 64 * 72 * 2);   // 57344 B
    cudaFuncSetAttribute(attn9_kernel,
                         cudaFuncAttributeMaxDynamicSharedMemorySize, attn_smem);
    dim3 ga(T_ / 128, H_, B_);       // (16, 16, 4)
    attn9_kernel<<<ga, 128, attn_smem>>>(qh, kh, vh, mp, ao);

    dim3 gg(D_ / 128, M / 128);      // (8, 64)
    gemm7_o_kernel<<<gg, 128, gemm_smem>>>(ao, wo_h, bo, q, xb);

    ln_kernel<<<M, 256>>>(xb, gamma, beta, out);
}

// round 16
// speedup vs baseline: 1.1250x; 1.1250x over previous
#include <cuda_runtime.h>
#include <cuda_fp16.h>
#include <cstdint>

#define B_  4
#define T_  2048
#define D_  1024
#define H_  16
#define DKH 64

// ---------------- scratch (static device globals; no runtime alloc) --------
__device__ __half g_qx[(size_t)B_ * T_ * D_];   // fp16 inputs
__device__ __half g_kx[(size_t)B_ * T_ * D_];
__device__ __half g_vx[(size_t)B_ * T_ * D_];
__device__ __half g_wh[4][(size_t)D_ * D_];     // fp16 weights [K,N]
__device__ __half g_qh[(size_t)B_ * T_ * D_];   // fp16 projections
__device__ __half g_kh[(size_t)B_ * T_ * D_];
__device__ __half g_vh[(size_t)B_ * T_ * D_];
__device__ __half g_ao[(size_t)B_ * T_ * D_];   // fp16 attention output
__device__ float  g_x [(size_t)B_ * T_ * D_];   // fp32 pre-LN
__device__ unsigned long long g_maskp[(size_t)B_ * T_ * (T_ / 64)];  // 2MB

// ---------------- cp.async / ldmatrix / mma helpers -------------------------
__device__ __forceinline__ void cp_async16(void* smem, const void* gmem) {
    unsigned s = (unsigned)__cvta_generic_to_shared(smem);
    asm volatile("cp.async.cg.shared.global [%0], [%1], 16;\n" :: "r"(s), "l"(gmem));
}
__device__ __forceinline__ void cp_async8(void* smem, const void* gmem) {
    unsigned s = (unsigned)__cvta_generic_to_shared(smem);
    asm volatile("cp.async.ca.shared.global [%0], [%1], 8;\n" :: "r"(s), "l"(gmem));
}
__device__ __forceinline__ void cp_commit() {
    asm volatile("cp.async.commit_group;\n");
}
template<int N>
__device__ __forceinline__ void cp_wait() {
    asm volatile("cp.async.wait_group %0;\n" :: "n"(N));
}
__device__ __forceinline__ void ldsm4(uint32_t* r, uint32_t a) {
    asm volatile("ldmatrix.sync.aligned.m8n8.x4.shared.b16 {%0,%1,%2,%3}, [%4];"
                 : "=r"(r[0]), "=r"(r[1]), "=r"(r[2]), "=r"(r[3]) : "r"(a));
}
__device__ __forceinline__ void ldsm4t(uint32_t* r, uint32_t a) {
    asm volatile("ldmatrix.sync.aligned.m8n8.x4.trans.shared.b16 {%0,%1,%2,%3}, [%4];"
                 : "=r"(r[0]), "=r"(r[1]), "=r"(r[2]), "=r"(r[3]) : "r"(a));
}
__device__ __forceinline__ void mma16816(float* c, const uint32_t* a, const uint32_t* b) {
    asm volatile(
        "mma.sync.aligned.m16n8k16.row.col.f32.f16.f16.f32 "
        "{%0,%1,%2,%3}, {%4,%5,%6,%7}, {%8,%9}, {%0,%1,%2,%3};"
        : "+f"(c[0]), "+f"(c[1]), "+f"(c[2]), "+f"(c[3])
        : "r"(a[0]), "r"(a[1]), "r"(a[2]), "r"(a[3]), "r"(b[0]), "r"(b[1]));
}
// pack two fp32 to fp16x2 (RTN)
__device__ __forceinline__ uint32_t pack_h2(float a, float b) {
    __half2 h = __floats2half2_rn(a, b);
    return *reinterpret_cast<uint32_t*>(&h);
}
// ex2 on fp16x2
__device__ __forceinline__ uint32_t ex2_h2(uint32_t t) {
    uint32_t r;
    asm volatile("ex2.approx.f16x2 %0, %1;" : "=r"(r) : "r"(t));
    return r;
}

// ---------------- mask bit-pack: one warp per 64-bit word -------------------
__global__ void pack_mask_kernel(const int* __restrict__ mask,
                                 unsigned long long* __restrict__ mp) {
    const int gw   = (blockIdx.x * blockDim.x + threadIdx.x) >> 5;
    const int lane = threadIdx.x & 31;
    const int* src = mask + (size_t)gw * 64;
    int v0 = src[lane];
    int v1 = src[lane + 32];
    unsigned lo = __ballot_sync(0xffffffffu, v0 != 0);
    unsigned hi = __ballot_sync(0xffffffffu, v1 != 0);
    if (lane == 0) mp[gw] = ((unsigned long long)hi << 32) | lo;
}

// ---------------- fp32 -> fp16 convert (batched) ----------------------------
__global__ void f2h3_kernel(const float* __restrict__ s0, __half* __restrict__ d0,
                            const float* __restrict__ s1, __half* __restrict__ d1,
                            const float* __restrict__ s2, __half* __restrict__ d2,
                            int n4) {
    int i = blockIdx.x * blockDim.x + threadIdx.x;
    if (i >= n4) return;
    const float* in = (blockIdx.y == 0) ? s0 : (blockIdx.y == 1) ? s1 : s2;
    __half* out     = (blockIdx.y == 0) ? d0 : (blockIdx.y == 1) ? d1 : d2;
    float4 v = ((const float4*)in)[i];
    ((__half2*)out)[2 * i + 0] = __floats2half2_rn(v.x, v.y);
    ((__half2*)out)[2 * i + 1] = __floats2half2_rn(v.z, v.w);
}
__global__ void f2h4_kernel(const float* __restrict__ s0, const float* __restrict__ s1,
                            const float* __restrict__ s2, const float* __restrict__ s3,
                            __half* __restrict__ dst, int n4) {
    int i = blockIdx.x * blockDim.x + threadIdx.x;
    if (i >= n4) return;
    const float* in = (blockIdx.y == 0) ? s0 : (blockIdx.y == 1) ? s1
                    : (blockIdx.y == 2) ? s2 : s3;
    __half* out = dst + (size_t)blockIdx.y * D_ * D_;
    float4 v = ((const float4*)in)[i];
    ((__half2*)out)[2 * i + 0] = __floats2half2_rn(v.x, v.y);
    ((__half2*)out)[2 * i + 1] = __floats2half2_rn(v.z, v.w);
}

// ---------------- GEMM v7: raw mma.sync, 128x128 tile, 4 warps, 3 CTAs/SM ---
template<bool OUT_HALF>
__device__ __forceinline__
void gemm7_body(const __half* __restrict__ A,
                const __half* __restrict__ W,
                const float* __restrict__ bias,
                const float* __restrict__ res,
                void* __restrict__ Cout,
                char* smraw) {
    constexpr int K = D_, N = D_;
    constexpr int LDA = 72, LDB = 136;
    constexpr int ASZ = 128 * LDA;          // halves per stage
    constexpr int BSZ = 64 * LDB;
    constexpr int NCH = K / 64;             // 16 k-chunks

    __half* sA = (__half*)smraw;            // 2 stages
    __half* sB = sA + 2 * ASZ;              // 2 stages

    const int tid  = threadIdx.x;
    const int warp = tid >> 5;
    const int lane = tid & 31;
    const int wr   = warp & 1;              // 64-row half
    const int wc   = warp >> 1;             // 64-col half
    const int lr   = lane & 15;
    const int lh   = (lane >> 4) & 1;
    const int gr   = lane >> 2;
    const int t4   = lane & 3;
    const int m0   = blockIdx.y * 128;
    const int n0   = blockIdx.x * 128;

    float acc[4][8][4];
    #pragma unroll
    for (int i = 0; i < 4; i++)
        #pragma unroll
        for (int j = 0; j < 8; j++)
            #pragma unroll
            for (int e = 0; e < 4; e++) acc[i][j][e] = 0.0f;

    auto load_chunk = [&](int ch, int st) {
        __half* a = sA + st * ASZ;
        __half* b = sB + st * BSZ;
        const int k0 = ch * 64;
        #pragma unroll
        for (int i = 0; i < 8; i++) {       // A: 128x64 halves = 1024 chunks
            int idx = tid + i * 128;
            int r = idx >> 3, c8 = idx & 7;
            cp_async16(a + r * LDA + c8 * 8, A + (size_t)(m0 + r) * K + k0 + c8 * 8);
        }
        #pragma unroll
        for (int i = 0; i < 8; i++) {       // B: 64x128 halves = 1024 chunks
            int idx = tid + i * 128;
            int r = idx >> 4, c8 = idx & 15;
            cp_async16(b + r * LDB + c8 * 8, W + (size_t)(k0 + r) * N + n0 + c8 * 8);
        }
        cp_commit();
    };

    load_chunk(0, 0);

    for (int ch = 0; ch < NCH; ch++) {
        cp_wait<0>();
        __syncthreads();
        if (ch + 1 < NCH) load_chunk(ch + 1, (ch + 1) & 1);

        const uint32_t aU = (uint32_t)__cvta_generic_to_shared(sA + (ch & 1) * ASZ);
        const uint32_t bU = (uint32_t)__cvta_generic_to_shared(sB + (ch & 1) * BSZ);

        #pragma unroll
        for (int kk = 0; kk < 4; kk++) {
            uint32_t af[4][4];
            uint32_t bf[4][4];
            #pragma unroll
            for (int i = 0; i < 4; i++)
                ldsm4(af[i], aU + 2u * ((wr * 64 + i * 16 + lr) * LDA + kk * 16 + lh * 8));
            #pragma unroll
            for (int j4 = 0; j4 < 4; j4++)
                ldsm4t(bf[j4], bU + 2u * ((kk * 16 + lr) * LDB + wc * 64 + j4 * 16 + lh * 8));
            #pragma unroll
            for (int i = 0; i < 4; i++)
                #pragma unroll
                for (int j = 0; j < 8; j++)
                    mma16816(acc[i][j], af[i], &bf[j >> 1][(j & 1) * 2]);
        }
    }

    // ---- epilogue: registers -> gmem, bias (+res) fused ----
    #pragma unroll
    for (int i = 0; i < 4; i++) {
        const size_t r0 = (size_t)(m0 + wr * 64 + i * 16 + gr);
        const size_t r1 = r0 + 8;
        #pragma unroll
        for (int j = 0; j < 8; j++) {
            const int c = n0 + wc * 64 + j * 8 + 2 * t4;
            float2 bb = *(const float2*)(bias + c);
            float v0 = acc[i][j][0] + bb.x, v1 = acc[i][j][1] + bb.y;
            float v2 = acc[i][j][2] + bb.x, v3 = acc[i][j][3] + bb.y;
            if (OUT_HALF) {
                *(__half2*)((__half*)Cout + r0 * N + c) = __floats2half2_rn(v0, v1);
                *(__half2*)((__half*)Cout + r1 * N + c) = __floats2half2_rn(v2, v3);
            } else {
                float2 ra = *(const float2*)(res + r0 * N + c);
                float2 rb = *(const float2*)(res + r1 * N + c);
                *(float2*)((float*)Cout + r0 * N + c) = make_float2(v0 + ra.x, v1 + ra.y);
                *(float2*)((float*)Cout + r1 * N + c) = make_float2(v2 + rb.x, v3 + rb.y);
            }
        }
    }
}

// fused QKV: blockIdx.z selects (A, W, bias, C)
__global__ __launch_bounds__(128, 3)
void gemm7_qkv_kernel(const __half* __restrict__ Aq, const __half* __restrict__ Ak,
                      const __half* __restrict__ Av, const __half* __restrict__ Wbase,
                      const float* __restrict__ bq, const float* __restrict__ bk,
                      const float* __restrict__ bv,
                      __half* __restrict__ Cq, __half* __restrict__ Ck,
                      __half* __restrict__ Cv) {
    extern __shared__ char smraw[];
    const int z = blockIdx.z;
    const __half* A = (z == 0) ? Aq : (z == 1) ? Ak : Av;
    const __half* W = Wbase + (size_t)z * D_ * D_;
    const float* bias = (z == 0) ? bq : (z == 1) ? bk : bv;
    __half* C = (z == 0) ? Cq : (z == 1) ? Ck : Cv;
    gemm7_body<true>(A, W, bias, nullptr, C, smraw);
}

// out-proj: fp32 out + residual
__global__ __launch_bounds__(128, 3)
void gemm7_o_kernel(const __half* __restrict__ A, const __half* __restrict__ W,
                    const float* __restrict__ bias, const float* __restrict__ res,
                    float* __restrict__ C) {
    extern __shared__ char smraw[];
    gemm7_body<false>(A, W, bias, res, C, smraw);
}

// ---------------- flash attention v10: attn8 + split K/V commit groups ------
// QR=64, 4 warps, 3 CTAs/SM. K+mask and V are separate cp.async groups so
// S-MMA starts as soon as K lands, while V (and next-tile loads) stream.
__global__ __launch_bounds__(128, 3)
void attn10_kernel(const __half* __restrict__ Qh,
                   const __half* __restrict__ Kh,
                   const __half* __restrict__ Vh,
                   const unsigned long long* __restrict__ maskp,
                   __half* __restrict__ Out) {
    constexpr int QR = 64, KT = 64, LD = 72;
    constexpr int NT = T_ / KT;   // 32
    constexpr float L2E = 1.44269504f;

    extern __shared__ char smraw[];
    unsigned long long* Mp = (unsigned long long*)smraw;        // 2*64*8 = 1024
    __half* Qs = (__half*)(smraw + 1024);                       // 64*72*2 = 9216
    __half* Ks = Qs + QR * LD;                                  // 2 stages 64*72
    __half* Vs = Ks + 2 * KT * LD;                              // 2 stages 64*72

    const int tid  = threadIdx.x;
    const int warp = tid >> 5;
    const int lane = tid & 31;
    const int q0   = blockIdx.x * QR;
    const int h    = blockIdx.y;
    const int b    = blockIdx.z;

    const int lr  = lane & 15;
    const int l7  = lane & 7;
    const int lh  = (lane >> 4) & 1;
    const int l8  = (lane >> 3) & 1;
    const int gr  = lane >> 2;
    const int t4  = lane & 3;

    const __half* Qg = Qh + ((size_t)b * T_ + q0) * D_ + h * DKH;

    // Q chunks (folded into first K group's commit)
    #pragma unroll
    for (int i = 0; i < 4; i++) {
        int idx = tid + i * 128;
        int r = idx >> 3, c8 = idx & 7;
        cp_async16(Qs + r * LD + c8 * 8, Qg + (size_t)r * D_ + c8 * 8);
    }

    // K + mask group (group A for tile kt)
    auto load_k = [&](int kt, int p) {
        const int k0 = kt * KT;
        const __half* Kg = Kh + ((size_t)b * T_ + k0) * D_ + h * DKH;
        __half* kd = Ks + p * KT * LD;
        #pragma unroll
        for (int i = 0; i < 4; i++) {
            int idx = tid + i * 128;
            int r = idx >> 3, c8 = idx & 7;
            cp_async16(kd + r * LD + c8 * 8, Kg + (size_t)r * D_ + c8 * 8);
        }
        if (tid < QR)
            cp_async8(&Mp[p * QR + tid],
                      &maskp[((size_t)b * T_ + q0 + tid) * (T_ / 64) + kt]);
        cp_commit();
    };
    // V group (group B for tile kt)
    auto load_v = [&](int kt, int p) {
        const int k0 = kt * KT;
        const __half* Vg = Vh + ((size_t)b * T_ + k0) * D_ + h * DKH;
        __half* vd = Vs + p * KT * LD;
        #pragma unroll
        for (int i = 0; i < 4; i++) {
            int idx = tid + i * 128;
            int r = idx >> 3, c8 = idx & 7;
            cp_async16(vd + r * LD + c8 * 8, Vg + (size_t)r * D_ + c8 * 8);
        }
        cp_commit();
    };

    load_k(0, 0);       // group: Q + K(0) + mask(0)
    load_v(0, 0);       // group: V(0)

    const uint32_t QsB = (uint32_t)__cvta_generic_to_shared(Qs);
    const uint32_t KsB = (uint32_t)__cvta_generic_to_shared(Ks);
    const uint32_t VsB = (uint32_t)__cvta_generic_to_shared(Vs);
    const uint32_t ONES2 = 0x3C003C00u;           // (1.0h, 1.0h)
    const uint32_t ob[2] = {ONES2, ONES2};

    uint32_t qa[4][4];
    float oc[8][4];
    #pragma unroll
    for (int j = 0; j < 8; j++)
        #pragma unroll
        for (int e = 0; e < 4; e++) oc[j][e] = 0.0f;

    float m0r = -1e30f, m1r = -1e30f;
    float l0r = 0.0f,  l1r = 0.0f;

    for (int kt = 0; kt < NT; kt++) {
        const int p = kt & 1;
        // Outstanding (oldest first): K(kt), V(kt). Wait for K(kt) only.
        cp_wait<1>();
        __syncthreads();            // stage p^1 consumers finished (prev iter)
        if (kt == 0) {
            #pragma unroll
            for (int kk = 0; kk < 4; kk++)
                ldsm4(qa[kk], QsB + 2u * ((warp * 16 + lr) * LD + kk * 16 + lh * 8));
        }
        if (kt + 1 < NT) {
            load_k(kt + 1, p ^ 1);  // outstanding: V(kt), K(kt+1)
            load_v(kt + 1, p ^ 1);  // outstanding: V(kt), K(kt+1), V(kt+1)
        }

        const uint32_t KdB = KsB + (uint32_t)(p * KT * LD * 2);
        const uint32_t VdB = VsB + (uint32_t)(p * KT * LD * 2);

        // ---- S = Q @ K^T (16 rows x 64 keys) ----
        float sc[8][4];
        #pragma unroll
        for (int j = 0; j < 8; j++)
            #pragma unroll
            for (int e = 0; e < 4; e++) sc[j][e] = 0.0f;

        #pragma unroll
        for (int kk = 0; kk < 4; kk++) {
            #pragma unroll
            for (int jp = 0; jp < 4; jp++) {
                uint32_t kb[4];
                ldsm4(kb, KdB + 2u * ((16 * jp + l7 + lh * 8) * LD + kk * 16 + l8 * 8));
                mma16816(sc[2 * jp],     qa[kk], kb);
                mma16816(sc[2 * jp + 1], qa[kk], kb + 2);
            }
        }

        // ---- row max over UNMASKED S (constant offset cancels in O/l) ----
        float mx0 = -1e30f, mx1 = -1e30f;
        #pragma unroll
        for (int j = 0; j < 8; j++) {
            mx0 = fmaxf(mx0, fmaxf(sc[j][0], sc[j][1]));
            mx1 = fmaxf(mx1, fmaxf(sc[j][2], sc[j][3]));
        }
        mx0 = fmaxf(mx0, __shfl_xor_sync(0xffffffffu, mx0, 1));
        mx0 = fmaxf(mx0, __shfl_xor_sync(0xffffffffu, mx0, 2));
        mx1 = fmaxf(mx1, __shfl_xor_sync(0xffffffffu, mx1, 1));
        mx1 = fmaxf(mx1, __shfl_xor_sync(0xffffffffu, mx1, 2));

        const float mn0 = fmaxf(m0r, mx0);
        const float mn1 = fmaxf(m1r, mx1);
        const float al0 = __expf(m0r - mn0);
        const float al1 = __expf(m1r - mn1);
        m0r = mn0; m1r = mn1;
        const float nm0 = mn0 * L2E;
        const float nm1 = mn1 * L2E;

        // ---- p = ex2((s-m)*log2e) in fp16x2, masked entries -> 0 ----
        const unsigned long long mm0 = Mp[p * QR + warp * 16 + gr];
        const unsigned long long mm1 = Mp[p * QR + warp * 16 + gr + 8];
        uint32_t pa[4][4];
        #pragma unroll
        for (int j = 0; j < 8; j++) {
            const int c0 = 8 * j + 2 * t4;
            float t0 = ((mm0 >> c0) & 1ull)       ? fmaf(sc[j][0], L2E, -nm0) : -1e4f;
            float t1 = ((mm0 >> (c0 + 1)) & 1ull) ? fmaf(sc[j][1], L2E, -nm0) : -1e4f;
            float t2 = ((mm1 >> c0) & 1ull)       ? fmaf(sc[j][2], L2E, -nm1) : -1e4f;
            float t3 = ((mm1 >> (c0 + 1)) & 1ull) ? fmaf(sc[j][3], L2E, -nm1) : -1e4f;
            const int kk = j >> 1, lohalf = (j & 1) << 1;
            pa[kk][lohalf + 0] = ex2_h2(pack_h2(t0, t1));
            pa[kk][lohalf + 1] = ex2_h2(pack_h2(t2, t3));
        }

        // ---- row sum l via tensor core: P @ ones ----
        float cs[4] = {0.0f, 0.0f, 0.0f, 0.0f};
        #pragma unroll
        for (int kk = 0; kk < 4; kk++)
            mma16816(cs, pa[kk], ob);
        l0r = l0r * al0 + cs[0];
        l1r = l1r * al1 + cs[2];

        #pragma unroll
        for (int j = 0; j < 8; j++) {
            oc[j][0] *= al0; oc[j][1] *= al0;
            oc[j][2] *= al1; oc[j][3] *= al1;
        }

        // ---- wait V(kt): keep K(kt+1), V(kt+1) outstanding ----
        if (kt + 1 < NT) { cp_wait<2>(); } else { cp_wait<0>(); }
        // NOTE: no extra barrier needed — every thread reads V only via its own
        // warp's ldmatrix after its own wait; V buffer writes were issued by the
        // same thread block before this point, and the stage-protection barrier
        // at loop top covers cross-iteration reuse.

        // ---- O += P @ V ----
        #pragma unroll
        for (int kk = 0; kk < 4; kk++) {
            #pragma unroll
            for (int jp = 0; jp < 4; jp++) {
                uint32_t vb[4];
                ldsm4t(vb, VdB + 2u * ((16 * kk + lr) * LD + 16 * jp + lh * 8));
                mma16816(oc[2 * jp],     pa[kk], vb);
                mma16816(oc[2 * jp + 1], pa[kk], vb + 2);
            }
        }
    }

    // ---- epilogue: O / (l + 1e-15), direct to gmem (fp16) ----
    const float inv0 = 1.0f / (l0r + 1e-15f);
    const float inv1 = 1.0f / (l1r + 1e-15f);
    const size_t row0 = (size_t)b * T_ + q0 + warp * 16 + gr;
    __half* o0 = Out + row0 * D_ + h * DKH;
    __half* o1 = o0 + 8 * D_;
    #pragma unroll
    for (int j = 0; j < 8; j++) {
        const int c = 8 * j + 2 * t4;
        *(__half2*)(o0 + c) = __floats2half2_rn(oc[j][0] * inv0, oc[j][1] * inv0);
        *(__half2*)(o1 + c) = __floats2half2_rn(oc[j][2] * inv1, oc[j][3] * inv1);
    }
}

// ---------------- LayerNorm over D=1024, one block per row -----------------
__global__ void ln_kernel(const float* __restrict__ X,
                          const float* __restrict__ gamma,
                          const float* __restrict__ beta,
                          float* __restrict__ Out) {
    const int row = blockIdx.x;
    const int tid = threadIdx.x;
    const float* x = X + (size_t)row * D_;

    __shared__ float red[8];
    __shared__ float s_mu, s_inv;

    float4 v = ((const float4*)x)[tid];
    float s = v.x + v.y + v.z + v.w;
    #pragma unroll
    for (int o = 16; o > 0; o >>= 1) s += __shfl_xor_sync(0xffffffffu, s, o);
    if ((tid & 31) == 0) red[tid >> 5] = s;
    __syncthreads();
    if (tid == 0) {
        float t = 0.0f;
        #pragma unroll
        for (int i = 0; i < 8; i++) t += red[i];
        s_mu = t * (1.0f / D_);
    }
    __syncthreads();
    const float mu = s_mu;

    float dx = v.x - mu, dy = v.y - mu, dz = v.z - mu, dw = v.w - mu;
    float s2 = dx * dx + dy * dy + dz * dz + dw * dw;
    #pragma unroll
    for (int o = 16; o > 0; o >>= 1) s2 += __shfl_xor_sync(0xffffffffu, s2, o);
    if ((tid & 31) == 0) red[tid >> 5] = s2;
    __syncthreads();
    if (tid == 0) {
        float t = 0.0f;
        #pragma unroll
        for (int i = 0; i < 8; i++) t += red[i];
        s_inv = rsqrtf(t * (1.0f / D_) + 1e-5f);
    }
    __syncthreads();
    const float inv = s_inv;

    const int c = tid * 4;
    float4 g = ((const float4*)(gamma + c))[0];
    float4 bb = ((const float4*)(beta + c))[0];
    float4 o;
    o.x = dx * inv * g.x + bb.x;
    o.y = dy * inv * g.y + bb.y;
    o.z = dz * inv * g.z + bb.z;
    o.w = dw * inv * g.w + bb.w;
    ((float4*)(Out + (size_t)row * D_))[tid] = o;
}

// ---------------- launch ----------------------------------------------------
extern "C" void kernel_launch(void* const* d_in, const int* in_sizes, int n_in,
                              void* d_out, int out_size) {
    const float* q     = (const float*)d_in[0];
    const float* k     = (const float*)d_in[1];
    const float* v     = (const float*)d_in[2];
    const int*   mask  = (const int*)  d_in[3];
    const float* Wq    = (const float*)d_in[4];
    const float* bq    = (const float*)d_in[5];
    const float* Wk    = (const float*)d_in[6];
    const float* bk    = (const float*)d_in[7];
    const float* Wv    = (const float*)d_in[8];
    const float* bv    = (const float*)d_in[9];
    const float* Wo    = (const float*)d_in[10];
    const float* bo    = (const float*)d_in[11];
    const float* gamma = (const float*)d_in[12];
    const float* beta  = (const float*)d_in[13];
    float* out = (float*)d_out;

    __half *qx, *kx, *vx, *wh, *qh, *kh, *vh, *ao;
    float *xb;
    unsigned long long* mp;
    cudaGetSymbolAddress((void**)&qx, g_qx);
    cudaGetSymbolAddress((void**)&kx, g_kx);
    cudaGetSymbolAddress((void**)&vx, g_vx);
    cudaGetSymbolAddress((void**)&wh, g_wh);
    cudaGetSymbolAddress((void**)&qh, g_qh);
    cudaGetSymbolAddress((void**)&kh, g_kh);
    cudaGetSymbolAddress((void**)&vh, g_vh);
    cudaGetSymbolAddress((void**)&ao, g_ao);
    cudaGetSymbolAddress((void**)&xb, g_x);
    cudaGetSymbolAddress((void**)&mp, g_maskp);

    __half* wo_h = wh + 3 * (size_t)D_ * D_;

    const int M = B_ * T_;   // 8192

    // pack mask to bits
    {
        const int words = B_ * T_ * (T_ / 64);
        pack_mask_kernel<<<words * 32 / 256, 256>>>(mask, mp);
    }

    // fp32 -> fp16 conversions (RTN), batched
    {
        const int n4a = (B_ * T_ * D_) / 4;
        dim3 ga(n4a / 256, 3);
        f2h3_kernel<<<ga, 256>>>(q, qx, k, kx, v, vx, n4a);
        const int n4w = (D_ * D_) / 4;
        dim3 gw(n4w / 256, 4);
        f2h4_kernel<<<gw, 256>>>(Wq, Wk, Wv, Wo, wh, n4w);
    }

    // mma.sync GEMMs (v7: 2-stage, direct register epilogue, 3 CTAs/SM)
    const int gemm_smem = 2 * (128 * 72 + 64 * 136) * 2;   // 71680 B
    cudaFuncSetAttribute(gemm7_qkv_kernel,
                         cudaFuncAttributeMaxDynamicSharedMemorySize, gemm_smem);
    cudaFuncSetAttribute(gemm7_o_kernel,
                         cudaFuncAttributeMaxDynamicSharedMemorySize, gemm_smem);

    dim3 gq(D_ / 128, M / 128, 3);   // (8, 64, 3)
    gemm7_qkv_kernel<<<gq, 128, gemm_smem>>>(qx, kx, vx, wh, bq, bk, bv,
                                             qh, kh, vh);

    // flash attention v10 (QR=64, 3 CTAs/SM, split K/V groups)
    const int attn_smem = 1024 + 64 * 72 * 2 + 2 * (2 * 64 * 72 * 2);   // 47104 B
    cudaFuncSetAttribute(attn10_kernel,
                         cudaFuncAttributeMaxDynamicSharedMemorySize, attn_smem);
    dim3 ga(T_ / 64, H_, B_);       // (32, 16, 4)
    attn10_kernel<<<ga, 128, attn_smem>>>(qh, kh, vh, mp, ao);

    dim3 gg(D_ / 128, M / 128);      // (8, 64)
    gemm7_o_kernel<<<gg, 128, gemm_smem>>>(ao, wo_h, bo, q, xb);

    ln_kernel<<<M, 256>>>(xb, gamma, beta, out);
}